// round 1
// baseline (speedup 1.0000x reference)
#include <cuda_runtime.h>
#include <cuda_bf16.h>
#include <math.h>

#define BB 2
#define QLEN 1024
#define MLEN 1024
#define KLEN 2048
#define EE 1024
#define HH 16
#define DH 64
#define HD 1024   // HH*DH
#define FF 4096

// ---------------- scratch (static device globals; no runtime alloc) ----------------
static __device__ float g_cat[(size_t)BB * KLEN * EE];          // 16MB
static __device__ float g_q  [(size_t)BB * QLEN * HD];          // 8MB
static __device__ float g_k  [(size_t)BB * KLEN * HD];          // 16MB
static __device__ float g_v  [(size_t)BB * KLEN * HD];          // 16MB
static __device__ float g_r  [(size_t)KLEN * HD];               // 8MB
static __device__ float g_bd [(size_t)BB * HH * QLEN * KLEN];   // 256MB
static __device__ float g_s  [(size_t)BB * HH * QLEN * KLEN];   // 256MB
static __device__ float g_att[(size_t)BB * QLEN * HD];          // 8MB
static __device__ float g_o  [(size_t)BB * QLEN * EE];          // 8MB
static __device__ float g_x  [(size_t)BB * QLEN * EE];          // 8MB
static __device__ float g_ffn[(size_t)BB * QLEN * FF];          // 32MB
static __device__ float g_y  [(size_t)BB * QLEN * EE];          // 8MB

// ---------------- cat = concat(member, w) along seq ----------------
__global__ __launch_bounds__(256) void copy_cat_kernel(
    const float* __restrict__ w, const float* __restrict__ member, float* __restrict__ cat)
{
    size_t i = (size_t)blockIdx.x * 256 + threadIdx.x;   // < BB*KLEN*EE
    int e  = (int)(i % EE);
    size_t t2 = i / EE;
    int kl = (int)(t2 % KLEN);
    int b  = (int)(t2 / KLEN);
    float v;
    if (kl < MLEN) v = member[((size_t)b * MLEN + kl) * EE + e];
    else           v = w[((size_t)b * QLEN + (kl - MLEN)) * EE + e];
    cat[i] = v;
}

// ---------------- generic fp32 tiled GEMM: C[M,N] = A[M,K] @ Bm[K,N] ----------------
// 64x64 tile, BK=16, 256 threads, 4x4 per thread. Optional fused ReLU.
__global__ __launch_bounds__(256) void gemm_kernel(
    const float* __restrict__ A, const float* __restrict__ Bm, float* __restrict__ C,
    int M, int N, int K, int relu)
{
    __shared__ __align__(16) float As[16][68];   // [k][m]
    __shared__ __align__(16) float Bs[16][68];   // [k][n]
    const int t  = threadIdx.x;
    const int ty = t >> 4, tx = t & 15;
    const int m0 = blockIdx.y * 64, n0 = blockIdx.x * 64;

    float acc[4][4] = {};
    for (int k0 = 0; k0 < K; k0 += 16) {
        #pragma unroll
        for (int j = 0; j < 4; j++) {
            int i = t + 256 * j;
            int r = i >> 4, c = i & 15;               // A tile 64x16
            As[c][r] = A[(size_t)(m0 + r) * K + (k0 + c)];
        }
        #pragma unroll
        for (int j = 0; j < 4; j++) {
            int i = t + 256 * j;
            int r = i >> 6, c = i & 63;               // B tile 16x64
            Bs[r][c] = Bm[(size_t)(k0 + r) * N + (n0 + c)];
        }
        __syncthreads();
        #pragma unroll
        for (int kk = 0; kk < 16; kk++) {
            float4 av = *(const float4*)&As[kk][ty * 4];
            float4 bv = *(const float4*)&Bs[kk][tx * 4];
            float a[4] = {av.x, av.y, av.z, av.w};
            float b[4] = {bv.x, bv.y, bv.z, bv.w};
            #pragma unroll
            for (int i = 0; i < 4; i++)
                #pragma unroll
                for (int j = 0; j < 4; j++)
                    acc[i][j] = fmaf(a[i], b[j], acc[i][j]);
        }
        __syncthreads();
    }
    #pragma unroll
    for (int i = 0; i < 4; i++) {
        int row = m0 + ty * 4 + i;
        float4 v;
        v.x = acc[i][0]; v.y = acc[i][1]; v.z = acc[i][2]; v.w = acc[i][3];
        if (relu) {
            v.x = fmaxf(v.x, 0.f); v.y = fmaxf(v.y, 0.f);
            v.z = fmaxf(v.z, 0.f); v.w = fmaxf(v.w, 0.f);
        }
        *(float4*)&C[(size_t)row * N + n0 + tx * 4] = v;
    }
}

// ---------------- BD_raw[b,h,q,j] = dot(qh[b,q,h,:] + rrb[h,:], rp[j,h,:]) ----------------
__global__ __launch_bounds__(256) void bd_kernel(
    const float* __restrict__ q, const float* __restrict__ rp,
    const float* __restrict__ rrb, float* __restrict__ BD)
{
    const int bh = blockIdx.z;
    const int b = bh / HH, h = bh % HH;
    const int q0 = blockIdx.y * 64, k0 = blockIdx.x * 64;
    __shared__ float Qs[64][65];   // [d][q]
    __shared__ float Rs[64][65];   // [d][k]
    const int t = threadIdx.x;
    const int ty = t >> 4, tx = t & 15;

    #pragma unroll
    for (int j = 0; j < 16; j++) {
        int i = t + 256 * j;
        int r = i >> 6, c = i & 63;
        if (j < 8) Qs[c][r] = q[(((size_t)b * QLEN + q0 + r) * HH + h) * DH + c] + rrb[h * DH + c];
        else       Rs[c][r - 64] = 0.f;  // placeholder (never hit; see below)
    }
    // do loads explicitly (both tiles are 64x64 = 4096 elems each, 16/thread each)
    #pragma unroll
    for (int j = 0; j < 16; j++) {
        int i = t + 256 * j;
        int r = i >> 6, c = i & 63;
        Qs[c][r] = q[(((size_t)b * QLEN + q0 + r) * HH + h) * DH + c] + rrb[h * DH + c];
        Rs[c][r] = rp[((size_t)(k0 + r) * HH + h) * DH + c];
    }
    __syncthreads();

    float acc[4][4] = {};
    #pragma unroll 8
    for (int kk = 0; kk < 64; kk++) {
        float a[4], bb[4];
        #pragma unroll
        for (int i = 0; i < 4; i++) a[i] = Qs[kk][ty * 4 + i];
        #pragma unroll
        for (int j = 0; j < 4; j++) bb[j] = Rs[kk][tx * 4 + j];
        #pragma unroll
        for (int i = 0; i < 4; i++)
            #pragma unroll
            for (int j = 0; j < 4; j++)
                acc[i][j] = fmaf(a[i], bb[j], acc[i][j]);
    }
    const size_t base = (size_t)bh * QLEN * KLEN;
    #pragma unroll
    for (int i = 0; i < 4; i++) {
        int qg = q0 + ty * 4 + i;
        float4 v; v.x = acc[i][0]; v.y = acc[i][1]; v.z = acc[i][2]; v.w = acc[i][3];
        *(float4*)&BD[base + (size_t)qg * KLEN + (k0 + tx * 4)] = v;
    }
}

// ---------------- S[b,h,q,k] = (AC + BD_raw[q, k - q + QLEN - 1]) * scale, masked ----------------
__global__ __launch_bounds__(256) void score_kernel(
    const float* __restrict__ q, const float* __restrict__ kmat,
    const float* __restrict__ rwb, const float* __restrict__ BD, float* __restrict__ S)
{
    const int bh = blockIdx.z;
    const int b = bh / HH, h = bh % HH;
    const int q0 = blockIdx.y * 64, k0 = blockIdx.x * 64;
    __shared__ float Qs[64][65];   // [d][q]
    __shared__ float Ks[64][65];   // [d][k]
    const int t = threadIdx.x;
    const int ty = t >> 4, tx = t & 15;

    #pragma unroll
    for (int j = 0; j < 16; j++) {
        int i = t + 256 * j;
        int r = i >> 6, c = i & 63;
        Qs[c][r] = q[(((size_t)b * QLEN + q0 + r) * HH + h) * DH + c] + rwb[h * DH + c];
        Ks[c][r] = kmat[(((size_t)b * KLEN + k0 + r) * HH + h) * DH + c];
    }
    __syncthreads();

    float acc[4][4] = {};
    #pragma unroll 8
    for (int kk = 0; kk < 64; kk++) {
        float a[4], bb[4];
        #pragma unroll
        for (int i = 0; i < 4; i++) a[i] = Qs[kk][ty * 4 + i];
        #pragma unroll
        for (int j = 0; j < 4; j++) bb[j] = Ks[kk][tx * 4 + j];
        #pragma unroll
        for (int i = 0; i < 4; i++)
            #pragma unroll
            for (int j = 0; j < 4; j++)
                acc[i][j] = fmaf(a[i], bb[j], acc[i][j]);
    }
    const float scale = 0.03125f;  // 1/sqrt(1024)
    const size_t base = (size_t)bh * QLEN * KLEN;
    #pragma unroll
    for (int i = 0; i < 4; i++) {
        int qg = q0 + ty * 4 + i;
        #pragma unroll
        for (int j = 0; j < 4; j++) {
            int kg = k0 + tx * 4 + j;
            float val;
            if (kg <= qg + MLEN) {
                int idx = kg + (QLEN - 1) - qg;   // rel_shift closed form, in [0, KLEN)
                val = (acc[i][j] + BD[base + (size_t)qg * KLEN + idx]) * scale;
            } else {
                val = -1e30f;
            }
            S[base + (size_t)qg * KLEN + kg] = val;
        }
    }
}

// ---------------- row softmax in place (rows of length KLEN) ----------------
__global__ __launch_bounds__(256) void softmax_kernel(float* __restrict__ S)
{
    __shared__ float red[256];
    const size_t row = blockIdx.x;
    float* p = S + row * KLEN;
    const int t = threadIdx.x;

    float vals[8];
    float m = -3.4e38f;
    #pragma unroll
    for (int j = 0; j < 8; j++) { vals[j] = p[t + 256 * j]; m = fmaxf(m, vals[j]); }
    red[t] = m; __syncthreads();
    for (int s = 128; s > 0; s >>= 1) { if (t < s) red[t] = fmaxf(red[t], red[t + s]); __syncthreads(); }
    m = red[0]; __syncthreads();

    float sum = 0.f;
    #pragma unroll
    for (int j = 0; j < 8; j++) { vals[j] = expf(vals[j] - m); sum += vals[j]; }
    red[t] = sum; __syncthreads();
    for (int s = 128; s > 0; s >>= 1) { if (t < s) red[t] += red[t + s]; __syncthreads(); }
    const float inv = 1.0f / red[0];
    #pragma unroll
    for (int j = 0; j < 8; j++) p[t + 256 * j] = vals[j] * inv;
}

// ---------------- O[b,q,h,d] = sum_k P[b,h,q,k] * v[b,k,h,d] ----------------
__global__ __launch_bounds__(256) void pv_kernel(
    const float* __restrict__ P, const float* __restrict__ V, float* __restrict__ O)
{
    const int bh = blockIdx.z;
    const int b = bh / HH, h = bh % HH;
    const int q0 = blockIdx.y * 64;
    const float* Prow = P + (size_t)bh * QLEN * KLEN;
    __shared__ float Ps[16][65];                   // [k][q]
    __shared__ __align__(16) float Vs[16][68];     // [k][d]
    const int t = threadIdx.x;
    const int ty = t >> 4, tx = t & 15;

    float acc[4][4] = {};
    for (int k0 = 0; k0 < KLEN; k0 += 16) {
        #pragma unroll
        for (int j = 0; j < 4; j++) {
            int i = t + 256 * j;
            int r = i >> 4, c = i & 15;            // P tile 64q x 16k
            Ps[c][r] = Prow[(size_t)(q0 + r) * KLEN + (k0 + c)];
        }
        #pragma unroll
        for (int j = 0; j < 4; j++) {
            int i = t + 256 * j;
            int r = i >> 6, c = i & 63;            // V tile 16k x 64d
            Vs[r][c] = V[(((size_t)b * KLEN + k0 + r) * HH + h) * DH + c];
        }
        __syncthreads();
        #pragma unroll
        for (int kk = 0; kk < 16; kk++) {
            float a[4];
            #pragma unroll
            for (int i = 0; i < 4; i++) a[i] = Ps[kk][ty * 4 + i];
            float4 bv = *(const float4*)&Vs[kk][tx * 4];
            float bb[4] = {bv.x, bv.y, bv.z, bv.w};
            #pragma unroll
            for (int i = 0; i < 4; i++)
                #pragma unroll
                for (int j = 0; j < 4; j++)
                    acc[i][j] = fmaf(a[i], bb[j], acc[i][j]);
        }
        __syncthreads();
    }
    #pragma unroll
    for (int i = 0; i < 4; i++) {
        int qg = q0 + ty * 4 + i;
        float4 v; v.x = acc[i][0]; v.y = acc[i][1]; v.z = acc[i][2]; v.w = acc[i][3];
        *(float4*)&O[(((size_t)b * QLEN + qg) * HH + h) * DH + tx * 4] = v;
    }
}

// ---------------- out = LayerNorm(a + b) * gamma + beta, rows of EE ----------------
__global__ __launch_bounds__(256) void add_ln_kernel(
    const float* __restrict__ A, const float* __restrict__ Bv,
    const float* __restrict__ gamma, const float* __restrict__ beta,
    float* __restrict__ out)
{
    __shared__ float red[256];
    const size_t row = blockIdx.x;
    const float* a = A + row * EE;
    const float* b = Bv + row * EE;
    float* o = out + row * EE;
    const int t = threadIdx.x;

    float v[4];
    float s = 0.f;
    #pragma unroll
    for (int j = 0; j < 4; j++) { v[j] = a[t + 256 * j] + b[t + 256 * j]; s += v[j]; }
    red[t] = s; __syncthreads();
    for (int st = 128; st > 0; st >>= 1) { if (t < st) red[t] += red[t + st]; __syncthreads(); }
    const float mean = red[0] * (1.0f / EE); __syncthreads();

    float s2 = 0.f;
    #pragma unroll
    for (int j = 0; j < 4; j++) { float d = v[j] - mean; s2 += d * d; }
    red[t] = s2; __syncthreads();
    for (int st = 128; st > 0; st >>= 1) { if (t < st) red[t] += red[t + st]; __syncthreads(); }
    const float var = red[0] * (1.0f / EE);
    const float inv = rsqrtf(var + 1e-3f);
    #pragma unroll
    for (int j = 0; j < 4; j++) {
        int c = t + 256 * j;
        o[c] = (v[j] - mean) * inv * gamma[c] + beta[c];
    }
}

// ---------------- launch ----------------
extern "C" void kernel_launch(void* const* d_in, const int* in_sizes, int n_in,
                              void* d_out, int out_size)
{
    const float* w      = (const float*)d_in[0];
    const float* r      = (const float*)d_in[1];
    const float* member = (const float*)d_in[2];
    // d_in[3] attn_mask: analytic, unused
    const float* Wq  = (const float*)d_in[4];
    const float* Wk  = (const float*)d_in[5];
    const float* Wv  = (const float*)d_in[6];
    const float* Wr  = (const float*)d_in[7];
    const float* Wo  = (const float*)d_in[8];
    const float* rwb = (const float*)d_in[9];
    const float* rrb = (const float*)d_in[10];
    const float* ln1g = (const float*)d_in[11];
    const float* ln1b = (const float*)d_in[12];
    const float* W1  = (const float*)d_in[13];
    const float* W2  = (const float*)d_in[14];
    const float* ln2g = (const float*)d_in[15];
    const float* ln2b = (const float*)d_in[16];
    float* out = (float*)d_out;

    static float *p_cat = nullptr, *p_q, *p_k, *p_v, *p_r, *p_bd, *p_s,
                 *p_att, *p_o, *p_x, *p_ffn, *p_y;
    if (!p_cat) {
        cudaGetSymbolAddress((void**)&p_cat, g_cat);
        cudaGetSymbolAddress((void**)&p_q,   g_q);
        cudaGetSymbolAddress((void**)&p_k,   g_k);
        cudaGetSymbolAddress((void**)&p_v,   g_v);
        cudaGetSymbolAddress((void**)&p_r,   g_r);
        cudaGetSymbolAddress((void**)&p_bd,  g_bd);
        cudaGetSymbolAddress((void**)&p_s,   g_s);
        cudaGetSymbolAddress((void**)&p_att, g_att);
        cudaGetSymbolAddress((void**)&p_o,   g_o);
        cudaGetSymbolAddress((void**)&p_x,   g_x);
        cudaGetSymbolAddress((void**)&p_ffn, g_ffn);
        cudaGetSymbolAddress((void**)&p_y,   g_y);
    }

    // 1. cat = concat(member, w)
    copy_cat_kernel<<<(BB * KLEN * EE) / 256, 256>>>(w, member, p_cat);

    // 2. projections
    gemm_kernel<<<dim3(HD / 64, BB * QLEN / 64), 256>>>(w,     Wq, p_q, BB * QLEN, HD, EE, 0);
    gemm_kernel<<<dim3(HD / 64, BB * KLEN / 64), 256>>>(p_cat, Wk, p_k, BB * KLEN, HD, EE, 0);
    gemm_kernel<<<dim3(HD / 64, BB * KLEN / 64), 256>>>(p_cat, Wv, p_v, BB * KLEN, HD, EE, 0);
    gemm_kernel<<<dim3(HD / 64, KLEN / 64),      256>>>(r,     Wr, p_r, KLEN,      HD, EE, 0);

    // 3. attention scores
    bd_kernel   <<<dim3(KLEN / 64, QLEN / 64, BB * HH), 256>>>(p_q, p_r, rrb, p_bd);
    score_kernel<<<dim3(KLEN / 64, QLEN / 64, BB * HH), 256>>>(p_q, p_k, rwb, p_bd, p_s);

    // 4. softmax
    softmax_kernel<<<BB * HH * QLEN, 256>>>(p_s);

    // 5. P @ V
    pv_kernel<<<dim3(1, QLEN / 64, BB * HH), 256>>>(p_s, p_v, p_att);

    // 6. output projection + LN1
    gemm_kernel<<<dim3(EE / 64, BB * QLEN / 64), 256>>>(p_att, Wo, p_o, BB * QLEN, EE, HD, 0);
    add_ln_kernel<<<BB * QLEN, 256>>>(w, p_o, ln1g, ln1b, p_x);

    // 7. FFN + LN2 -> out
    gemm_kernel<<<dim3(FF / 64, BB * QLEN / 64), 256>>>(p_x,   W1, p_ffn, BB * QLEN, FF, EE, 1);
    gemm_kernel<<<dim3(EE / 64, BB * QLEN / 64), 256>>>(p_ffn, W2, p_y,   BB * QLEN, EE, FF, 0);
    add_ln_kernel<<<BB * QLEN, 256>>>(p_y, p_x, ln2g, ln2b, out);
}

// round 2
// speedup vs baseline: 2.5903x; 2.5903x over previous
#include <cuda_runtime.h>
#include <cuda_bf16.h>
#include <math.h>

#define BB 2
#define QLEN 1024
#define MLEN 1024
#define KLEN 2048
#define EE 1024
#define HH 16
#define DH 64
#define HD 1024   // HH*DH
#define FF 4096

// ---------------- scratch ----------------
static __device__ float g_cat[(size_t)BB * KLEN * EE];
static __device__ float g_q  [(size_t)BB * QLEN * HD];
static __device__ float g_k  [(size_t)BB * KLEN * HD];
static __device__ float g_v  [(size_t)BB * KLEN * HD];
static __device__ float g_r  [(size_t)KLEN * HD];
static __device__ float g_bd [(size_t)BB * HH * QLEN * KLEN];
static __device__ float g_s  [(size_t)BB * HH * QLEN * KLEN];
static __device__ float g_att[(size_t)BB * QLEN * HD];
static __device__ float g_o  [(size_t)BB * QLEN * EE];
static __device__ float g_x  [(size_t)BB * QLEN * EE];
static __device__ float g_ffn[(size_t)BB * QLEN * FF];
static __device__ float g_y  [(size_t)BB * QLEN * EE];

// ---------------- helpers ----------------
__device__ __forceinline__ unsigned f2t(float x) {
    unsigned u; asm("cvt.rna.tf32.f32 %0, %1;" : "=r"(u) : "f"(x)); return u;
}
__device__ __forceinline__ void mma8(float* c, const unsigned* a, const unsigned* b) {
    asm volatile("mma.sync.aligned.m16n8k8.row.col.f32.tf32.tf32.f32 "
        "{%0,%1,%2,%3}, {%4,%5,%6,%7}, {%8,%9}, {%0,%1,%2,%3};\n"
        : "+f"(c[0]), "+f"(c[1]), "+f"(c[2]), "+f"(c[3])
        : "r"(a[0]), "r"(a[1]), "r"(a[2]), "r"(a[3]), "r"(b[0]), "r"(b[1]));
}

// ---------------- cat = concat(member, w) ----------------
__global__ __launch_bounds__(256) void copy_cat_kernel(
    const float4* __restrict__ w, const float4* __restrict__ member, float4* __restrict__ cat)
{
    size_t i = (size_t)blockIdx.x * 256 + threadIdx.x;   // float4 index < BB*KLEN*EE/4
    int e4 = (int)(i % (EE / 4));
    size_t t2 = i / (EE / 4);
    int kl = (int)(t2 % KLEN);
    int b  = (int)(t2 / KLEN);
    float4 v;
    if (kl < MLEN) v = member[((size_t)b * MLEN + kl) * (EE / 4) + e4];
    else           v = w[((size_t)b * QLEN + (kl - MLEN)) * (EE / 4) + e4];
    cat[i] = v;
}

// ================= tf32 MMA GEMM, NN: C[M,N] = A[M,K] @ B[K,N] =================
// Block tile 128x128, BK=16, 256 threads, warp tile 64x32. Optional ReLU, batched via z.
__global__ __launch_bounds__(256, 2) void gemm_nn_tf32(
    const float* __restrict__ A, int lda, const float* __restrict__ B, int ldb,
    float* __restrict__ C, int ldc, int N, int K, int relu,
    size_t aSb, size_t aSh, size_t bSb, size_t bSh, size_t cSb, size_t cSh)
{
    const int zb = blockIdx.z >> 4, zh = blockIdx.z & 15;
    A += (size_t)zb * aSb + (size_t)zh * aSh;
    B += (size_t)zb * bSb + (size_t)zh * bSh;
    C += (size_t)zb * cSb + (size_t)zh * cSh;

    __shared__ __align__(16) unsigned As[2][128][20];
    __shared__ __align__(16) unsigned Bs[2][16][136];

    const int t = threadIdx.x;
    const int lane = t & 31, warp = t >> 5;
    const int g = lane >> 2, tig = lane & 3;
    const int wm0 = (warp >> 2) * 64, wn0 = (warp & 3) * 32;
    const int m0 = blockIdx.y * 128, n0 = blockIdx.x * 128;

    const int arow = t >> 2,  akc = (t & 3) * 4;    // A: (row, row+64) x 4 cols
    const int brow = t >> 5,  bnc = (t & 31) * 4;   // B: (row, row+8)  x 4 cols

    float c[4][4][4] = {};

    // preload tile 0
    {
        #pragma unroll
        for (int j = 0; j < 2; j++) {
            int row = arow + 64 * j;
            float4 f = *(const float4*)&A[(size_t)(m0 + row) * lda + akc];
            As[0][row][akc + 0] = f2t(f.x); As[0][row][akc + 1] = f2t(f.y);
            As[0][row][akc + 2] = f2t(f.z); As[0][row][akc + 3] = f2t(f.w);
        }
        #pragma unroll
        for (int j = 0; j < 2; j++) {
            int row = brow + 8 * j;
            int n = n0 + bnc;
            float4 f = make_float4(0.f, 0.f, 0.f, 0.f);
            if (n < N) f = *(const float4*)&B[(size_t)row * ldb + n];
            Bs[0][row][bnc + 0] = f2t(f.x); Bs[0][row][bnc + 1] = f2t(f.y);
            Bs[0][row][bnc + 2] = f2t(f.z); Bs[0][row][bnc + 3] = f2t(f.w);
        }
    }
    __syncthreads();

    const int nk = K / 16;
    int buf = 0;
    for (int kt = 0; kt < nk; kt++) {
        float4 ra[2], rb[2];
        if (kt + 1 < nk) {
            int k0 = (kt + 1) * 16;
            #pragma unroll
            for (int j = 0; j < 2; j++)
                ra[j] = *(const float4*)&A[(size_t)(m0 + arow + 64 * j) * lda + k0 + akc];
            #pragma unroll
            for (int j = 0; j < 2; j++) {
                int n = n0 + bnc;
                rb[j] = make_float4(0.f, 0.f, 0.f, 0.f);
                if (n < N) rb[j] = *(const float4*)&B[(size_t)(k0 + brow + 8 * j) * ldb + n];
            }
        }
        // compute on buf
        #pragma unroll
        for (int ks = 0; ks < 16; ks += 8) {
            unsigned af[4][4], bf[4][2];
            #pragma unroll
            for (int mi = 0; mi < 4; mi++) {
                int m = wm0 + mi * 16 + g;
                af[mi][0] = As[buf][m][ks + tig];
                af[mi][1] = As[buf][m + 8][ks + tig];
                af[mi][2] = As[buf][m][ks + tig + 4];
                af[mi][3] = As[buf][m + 8][ks + tig + 4];
            }
            #pragma unroll
            for (int ni = 0; ni < 4; ni++) {
                int n = wn0 + ni * 8 + g;
                bf[ni][0] = Bs[buf][ks + tig][n];
                bf[ni][1] = Bs[buf][ks + tig + 4][n];
            }
            #pragma unroll
            for (int mi = 0; mi < 4; mi++)
                #pragma unroll
                for (int ni = 0; ni < 4; ni++)
                    mma8(c[mi][ni], af[mi], bf[ni]);
        }
        if (kt + 1 < nk) {
            int nb = buf ^ 1;
            #pragma unroll
            for (int j = 0; j < 2; j++) {
                int row = arow + 64 * j;
                As[nb][row][akc + 0] = f2t(ra[j].x); As[nb][row][akc + 1] = f2t(ra[j].y);
                As[nb][row][akc + 2] = f2t(ra[j].z); As[nb][row][akc + 3] = f2t(ra[j].w);
            }
            #pragma unroll
            for (int j = 0; j < 2; j++) {
                int row = brow + 8 * j;
                Bs[nb][row][bnc + 0] = f2t(rb[j].x); Bs[nb][row][bnc + 1] = f2t(rb[j].y);
                Bs[nb][row][bnc + 2] = f2t(rb[j].z); Bs[nb][row][bnc + 3] = f2t(rb[j].w);
            }
            __syncthreads();
        }
        buf ^= 1;
    }

    // epilogue
    #pragma unroll
    for (int mi = 0; mi < 4; mi++) {
        int row = m0 + wm0 + mi * 16 + g;
        #pragma unroll
        for (int ni = 0; ni < 4; ni++) {
            int col = n0 + wn0 + ni * 8 + 2 * tig;
            if (col < N) {
                float2 v0 = make_float2(c[mi][ni][0], c[mi][ni][1]);
                float2 v1 = make_float2(c[mi][ni][2], c[mi][ni][3]);
                if (relu) {
                    v0.x = fmaxf(v0.x, 0.f); v0.y = fmaxf(v0.y, 0.f);
                    v1.x = fmaxf(v1.x, 0.f); v1.y = fmaxf(v1.y, 0.f);
                }
                *(float2*)&C[(size_t)row * ldc + col] = v0;
                *(float2*)&C[(size_t)(row + 8) * ldc + col] = v1;
            }
        }
    }
}

// ================= tf32 MMA, NT with A-bias: attention AC/BD =================
// C[M,N] = (A + bias)[M,K] @ B[N,K]^T, K=64. mode 0: plain store (BD_raw).
// mode 1: score epilogue: S = (acc + BD[q, k-q+QLEN-1]) * scale, masked.
__global__ __launch_bounds__(256, 2) void attn_nt_tf32(
    const float* __restrict__ A, const float* __restrict__ B,
    const float* __restrict__ bias, float* __restrict__ C,
    const float* __restrict__ BDg, int mode,
    size_t bSb, size_t bSh)
{
    const int zbh = blockIdx.z;
    const int zb = zbh >> 4, zh = zbh & 15;
    A += ((size_t)zb * QLEN) * HD + (size_t)zh * DH;
    B += (size_t)zb * bSb + (size_t)zh * bSh;
    C += (size_t)zbh * QLEN * KLEN;
    const float* BD = BDg + (size_t)zbh * QLEN * KLEN;
    bias += zh * DH;

    __shared__ __align__(16) unsigned As[2][128][20];
    __shared__ __align__(16) unsigned Bs[2][128][20];

    const int t = threadIdx.x;
    const int lane = t & 31, warp = t >> 5;
    const int g = lane >> 2, tig = lane & 3;
    const int wm0 = (warp >> 2) * 64, wn0 = (warp & 3) * 32;
    const int m0 = blockIdx.y * 128, n0 = blockIdx.x * 128;

    const int arow = t >> 2, akc = (t & 3) * 4;

    float c[4][4][4] = {};

    // preload tile 0 (k0=0)
    {
        float4 bs = *(const float4*)&bias[akc];
        #pragma unroll
        for (int j = 0; j < 2; j++) {
            int row = arow + 64 * j;
            float4 f = *(const float4*)&A[(size_t)(m0 + row) * HD + akc];
            As[0][row][akc + 0] = f2t(f.x + bs.x); As[0][row][akc + 1] = f2t(f.y + bs.y);
            As[0][row][akc + 2] = f2t(f.z + bs.z); As[0][row][akc + 3] = f2t(f.w + bs.w);
        }
        #pragma unroll
        for (int j = 0; j < 2; j++) {
            int row = arow + 64 * j;
            float4 f = *(const float4*)&B[(size_t)(n0 + row) * HD + akc];
            Bs[0][row][akc + 0] = f2t(f.x); Bs[0][row][akc + 1] = f2t(f.y);
            Bs[0][row][akc + 2] = f2t(f.z); Bs[0][row][akc + 3] = f2t(f.w);
        }
    }
    __syncthreads();

    int buf = 0;
    #pragma unroll
    for (int kt = 0; kt < 4; kt++) {          // K = 64 = 4 * 16
        float4 ra[2], rb[2], bs;
        if (kt < 3) {
            int k0 = (kt + 1) * 16;
            bs = *(const float4*)&bias[k0 + akc];
            #pragma unroll
            for (int j = 0; j < 2; j++)
                ra[j] = *(const float4*)&A[(size_t)(m0 + arow + 64 * j) * HD + k0 + akc];
            #pragma unroll
            for (int j = 0; j < 2; j++)
                rb[j] = *(const float4*)&B[(size_t)(n0 + arow + 64 * j) * HD + k0 + akc];
        }
        #pragma unroll
        for (int ks = 0; ks < 16; ks += 8) {
            unsigned af[4][4], bf[4][2];
            #pragma unroll
            for (int mi = 0; mi < 4; mi++) {
                int m = wm0 + mi * 16 + g;
                af[mi][0] = As[buf][m][ks + tig];
                af[mi][1] = As[buf][m + 8][ks + tig];
                af[mi][2] = As[buf][m][ks + tig + 4];
                af[mi][3] = As[buf][m + 8][ks + tig + 4];
            }
            #pragma unroll
            for (int ni = 0; ni < 4; ni++) {
                int n = wn0 + ni * 8 + g;
                bf[ni][0] = Bs[buf][n][ks + tig];
                bf[ni][1] = Bs[buf][n][ks + tig + 4];
            }
            #pragma unroll
            for (int mi = 0; mi < 4; mi++)
                #pragma unroll
                for (int ni = 0; ni < 4; ni++)
                    mma8(c[mi][ni], af[mi], bf[ni]);
        }
        if (kt < 3) {
            int nb = buf ^ 1;
            #pragma unroll
            for (int j = 0; j < 2; j++) {
                int row = arow + 64 * j;
                As[nb][row][akc + 0] = f2t(ra[j].x + bs.x); As[nb][row][akc + 1] = f2t(ra[j].y + bs.y);
                As[nb][row][akc + 2] = f2t(ra[j].z + bs.z); As[nb][row][akc + 3] = f2t(ra[j].w + bs.w);
                Bs[nb][row][akc + 0] = f2t(rb[j].x); Bs[nb][row][akc + 1] = f2t(rb[j].y);
                Bs[nb][row][akc + 2] = f2t(rb[j].z); Bs[nb][row][akc + 3] = f2t(rb[j].w);
            }
            __syncthreads();
        }
        buf ^= 1;
    }

    const float scale = 0.03125f;  // 1/sqrt(1024)
    #pragma unroll
    for (int mi = 0; mi < 4; mi++) {
        #pragma unroll
        for (int ni = 0; ni < 4; ni++) {
            int col = n0 + wn0 + ni * 8 + 2 * tig;
            #pragma unroll
            for (int half = 0; half < 2; half++) {
                int row = m0 + wm0 + mi * 16 + g + 8 * half;
                float a0 = c[mi][ni][2 * half + 0];
                float a1 = c[mi][ni][2 * half + 1];
                if (mode == 0) {
                    *(float2*)&C[(size_t)row * KLEN + col] = make_float2(a0, a1);
                } else {
                    float2 o;
                    const float* bdrow = BD + (size_t)row * KLEN;
                    int i0 = col + (QLEN - 1) - row;
                    o.x = (col     <= row + MLEN) ? (a0 + bdrow[i0    ]) * scale : -1e30f;
                    o.y = (col + 1 <= row + MLEN) ? (a1 + bdrow[i0 + 1]) * scale : -1e30f;
                    *(float2*)&C[(size_t)row * KLEN + col] = o;
                }
            }
        }
    }
}

// ---------------- row softmax, rows of KLEN (float4 vectorized) ----------------
__global__ __launch_bounds__(256) void softmax_kernel(float* __restrict__ S)
{
    __shared__ float red[256];
    float4* p = (float4*)(S + (size_t)blockIdx.x * KLEN);
    const int t = threadIdx.x;

    float4 v[2];
    v[0] = p[t]; v[1] = p[t + 256];
    float m = fmaxf(fmaxf(fmaxf(v[0].x, v[0].y), fmaxf(v[0].z, v[0].w)),
                    fmaxf(fmaxf(v[1].x, v[1].y), fmaxf(v[1].z, v[1].w)));
    red[t] = m; __syncthreads();
    for (int s = 128; s > 0; s >>= 1) { if (t < s) red[t] = fmaxf(red[t], red[t + s]); __syncthreads(); }
    m = red[0]; __syncthreads();

    float sum = 0.f;
    #pragma unroll
    for (int j = 0; j < 2; j++) {
        v[j].x = __expf(v[j].x - m); v[j].y = __expf(v[j].y - m);
        v[j].z = __expf(v[j].z - m); v[j].w = __expf(v[j].w - m);
        sum += v[j].x + v[j].y + v[j].z + v[j].w;
    }
    red[t] = sum; __syncthreads();
    for (int s = 128; s > 0; s >>= 1) { if (t < s) red[t] += red[t + s]; __syncthreads(); }
    const float inv = 1.0f / red[0];
    #pragma unroll
    for (int j = 0; j < 2; j++) {
        v[j].x *= inv; v[j].y *= inv; v[j].z *= inv; v[j].w *= inv;
    }
    p[t] = v[0]; p[t + 256] = v[1];
}

// ---------------- out = LayerNorm(a + b), rows of EE ----------------
__global__ __launch_bounds__(256) void add_ln_kernel(
    const float* __restrict__ A, const float* __restrict__ Bv,
    const float* __restrict__ gamma, const float* __restrict__ beta,
    float* __restrict__ out)
{
    __shared__ float red[256];
    const size_t row = blockIdx.x;
    const int t = threadIdx.x;
    float4 va = ((const float4*)(A + row * EE))[t];
    float4 vb = ((const float4*)(Bv + row * EE))[t];
    float4 v = make_float4(va.x + vb.x, va.y + vb.y, va.z + vb.z, va.w + vb.w);

    red[t] = v.x + v.y + v.z + v.w; __syncthreads();
    for (int s = 128; s > 0; s >>= 1) { if (t < s) red[t] += red[t + s]; __syncthreads(); }
    const float mean = red[0] * (1.0f / EE); __syncthreads();

    float dx = v.x - mean, dy = v.y - mean, dz = v.z - mean, dw = v.w - mean;
    red[t] = dx * dx + dy * dy + dz * dz + dw * dw; __syncthreads();
    for (int s = 128; s > 0; s >>= 1) { if (t < s) red[t] += red[t + s]; __syncthreads(); }
    const float inv = rsqrtf(red[0] * (1.0f / EE) + 1e-3f);

    float4 gm = ((const float4*)gamma)[t];
    float4 bt = ((const float4*)beta)[t];
    float4 o;
    o.x = dx * inv * gm.x + bt.x; o.y = dy * inv * gm.y + bt.y;
    o.z = dz * inv * gm.z + bt.z; o.w = dw * inv * gm.w + bt.w;
    ((float4*)(out + row * EE))[t] = o;
}

// ---------------- launch ----------------
extern "C" void kernel_launch(void* const* d_in, const int* in_sizes, int n_in,
                              void* d_out, int out_size)
{
    const float* w      = (const float*)d_in[0];
    const float* r      = (const float*)d_in[1];
    const float* member = (const float*)d_in[2];
    const float* Wq  = (const float*)d_in[4];
    const float* Wk  = (const float*)d_in[5];
    const float* Wv  = (const float*)d_in[6];
    const float* Wr  = (const float*)d_in[7];
    const float* Wo  = (const float*)d_in[8];
    const float* rwb = (const float*)d_in[9];
    const float* rrb = (const float*)d_in[10];
    const float* ln1g = (const float*)d_in[11];
    const float* ln1b = (const float*)d_in[12];
    const float* W1  = (const float*)d_in[13];
    const float* W2  = (const float*)d_in[14];
    const float* ln2g = (const float*)d_in[15];
    const float* ln2b = (const float*)d_in[16];
    float* out = (float*)d_out;

    static float *p_cat = nullptr, *p_q, *p_k, *p_v, *p_r, *p_bd, *p_s,
                 *p_att, *p_o, *p_x, *p_ffn, *p_y;
    if (!p_cat) {
        cudaGetSymbolAddress((void**)&p_cat, g_cat);
        cudaGetSymbolAddress((void**)&p_q,   g_q);
        cudaGetSymbolAddress((void**)&p_k,   g_k);
        cudaGetSymbolAddress((void**)&p_v,   g_v);
        cudaGetSymbolAddress((void**)&p_r,   g_r);
        cudaGetSymbolAddress((void**)&p_bd,  g_bd);
        cudaGetSymbolAddress((void**)&p_s,   g_s);
        cudaGetSymbolAddress((void**)&p_att, g_att);
        cudaGetSymbolAddress((void**)&p_o,   g_o);
        cudaGetSymbolAddress((void**)&p_x,   g_x);
        cudaGetSymbolAddress((void**)&p_ffn, g_ffn);
        cudaGetSymbolAddress((void**)&p_y,   g_y);
    }

    // 1. cat
    copy_cat_kernel<<<(BB * KLEN * EE / 4) / 256, 256>>>(
        (const float4*)w, (const float4*)member, (float4*)p_cat);

    // 2. projections (tf32 MMA)
    gemm_nn_tf32<<<dim3(HD / 128, (BB * QLEN) / 128), 256>>>(w,     EE, Wq, HD, p_q, HD, HD, EE, 0, 0,0,0,0,0,0);
    gemm_nn_tf32<<<dim3(HD / 128, (BB * KLEN) / 128), 256>>>(p_cat, EE, Wk, HD, p_k, HD, HD, EE, 0, 0,0,0,0,0,0);
    gemm_nn_tf32<<<dim3(HD / 128, (BB * KLEN) / 128), 256>>>(p_cat, EE, Wv, HD, p_v, HD, HD, EE, 0, 0,0,0,0,0,0);
    gemm_nn_tf32<<<dim3(HD / 128, KLEN / 128),        256>>>(r,     EE, Wr, HD, p_r, HD, HD, EE, 0, 0,0,0,0,0,0);

    // 3. BD_raw then masked scores (AC + shifted BD)
    attn_nt_tf32<<<dim3(KLEN / 128, QLEN / 128, BB * HH), 256>>>(
        p_q, p_r, rrb, p_bd, p_bd, 0, 0, (size_t)DH);
    attn_nt_tf32<<<dim3(KLEN / 128, QLEN / 128, BB * HH), 256>>>(
        p_q, p_k, rwb, p_s, p_bd, 1, (size_t)KLEN * HD, (size_t)DH);

    // 4. softmax
    softmax_kernel<<<BB * HH * QLEN, 256>>>(p_s);

    // 5. P @ V  (batched per (b,h), N=64)
    gemm_nn_tf32<<<dim3(1, QLEN / 128, BB * HH), 256>>>(
        p_s, KLEN, p_v, HD, p_att, HD, DH, KLEN, 0,
        (size_t)HH * QLEN * KLEN, (size_t)QLEN * KLEN,
        (size_t)KLEN * HD, (size_t)DH,
        (size_t)QLEN * HD, (size_t)DH);

    // 6. output projection + LN1
    gemm_nn_tf32<<<dim3(EE / 128, (BB * QLEN) / 128), 256>>>(p_att, HD, Wo, EE, p_o, EE, EE, HD, 0, 0,0,0,0,0,0);
    add_ln_kernel<<<BB * QLEN, 256>>>(w, p_o, ln1g, ln1b, p_x);

    // 7. FFN + LN2 -> out
    gemm_nn_tf32<<<dim3(FF / 128, (BB * QLEN) / 128), 256>>>(p_x,   EE, W1, FF, p_ffn, FF, FF, EE, 1, 0,0,0,0,0,0);
    gemm_nn_tf32<<<dim3(EE / 128, (BB * QLEN) / 128), 256>>>(p_ffn, FF, W2, EE, p_y,   EE, EE, FF, 0, 0,0,0,0,0,0);
    add_ln_kernel<<<BB * QLEN, 256>>>(p_y, p_x, ln2g, ln2b, out);
}